// round 2
// baseline (speedup 1.0000x reference)
#include <cuda_runtime.h>
#include <math.h>

#define BATCH 2
#define TT 16
#define CC 128
#define HW 2304
#define NPIX 2304
#define DI 256
#define DS 16
#define KKEEP 1152
#define NSEQ (BATCH*KKEEP)

// scratch (static device globals; no allocations allowed)
__device__ float g_energy[BATCH*NPIX];
__device__ int   g_idx[BATCH*KKEEP];
__device__ float g_zbuf[(size_t)NSEQ*TT*CC];

// ---------------------------------------------------------------- copy base
__global__ void k_copy(const float4* __restrict__ src, float4* __restrict__ dst, int n4){
    int i = blockIdx.x*blockDim.x + threadIdx.x;
    if (i < n4) dst[i] = src[i];
}

// ---------------------------------------------------------------- energy
__global__ void k_energy(const float* __restrict__ x){
    int id = blockIdx.x*blockDim.x + threadIdx.x;
    if (id >= BATCH*NPIX) return;
    int b = id / NPIX, n = id % NPIX;
    const float* xb = x + (size_t)b*TT*CC*HW + n;
    float e = 0.f;
    for (int t = 0; t < TT; t++){
        const float* xt = xb + (size_t)t*CC*HW;
        float ss = 0.f;
        #pragma unroll 8
        for (int c = 0; c < CC; c++){
            float v = xt[(size_t)c*HW];
            ss += v*v;
        }
        e += sqrtf(ss);
    }
    g_energy[id] = e * (1.f/TT);
}

// ---------------------------------------------------------------- select top-K (stable rank), sorted index output
__global__ void k_select(){
    __shared__ float se[NPIX];
    __shared__ int scnt[768];
    int b = blockIdx.x, tid = threadIdx.x;   // 768 threads, 3 pixels each
    for (int i = tid; i < NPIX; i += 768) se[i] = g_energy[b*NPIX + i];
    __syncthreads();
    int n0 = tid*3;
    float e0 = se[n0], e1 = se[n0+1], e2 = se[n0+2];
    int r0 = 0, r1 = 0, r2 = 0;
    for (int m = 0; m < NPIX; m++){
        float em = se[m];
        r0 += (em > e0) || (em == e0 && m < n0);
        r1 += (em > e1) || (em == e1 && m < n0+1);
        r2 += (em > e2) || (em == e2 && m < n0+2);
    }
    int k0 = r0 < KKEEP, k1 = r1 < KKEEP, k2 = r2 < KKEEP;
    int cnt = k0 + k1 + k2;
    scnt[tid] = cnt;
    __syncthreads();
    // Hillis-Steele inclusive scan over 768 counts
    for (int off = 1; off < 768; off <<= 1){
        int add = (tid >= off) ? scnt[tid-off] : 0;
        __syncthreads();
        scnt[tid] += add;
        __syncthreads();
    }
    int pos = scnt[tid] - cnt;
    if (k0) g_idx[b*KKEEP + pos++] = n0;
    if (k1) g_idx[b*KKEEP + pos++] = n0+1;
    if (k2) g_idx[b*KKEEP + pos++] = n0+2;
}

// ---------------------------------------------------------------- fused mamba per sequence
// smem floats: sx 2048 | sw 10400 | sxi 4096 | szg 4096 | sdt 128 | sB 256 | sC 256  = 21280 (85120 B)
#define SMEM_C_FLOATS 21280
__global__ void __launch_bounds__(256)
k_mamba(const float* __restrict__ x,
        const float* __restrict__ norm1_w,
        const float* __restrict__ in_w,
        const float* __restrict__ conv_w,
        const float* __restrict__ conv_b,
        const float* __restrict__ xp_w,
        const float* __restrict__ dt_w,
        const float* __restrict__ dt_b,
        const float* __restrict__ A_log,
        const float* __restrict__ Dp,
        const float* __restrict__ out_w){
    extern __shared__ float sm[];
    float* sx  = sm;             // [16][128]
    float* sw  = sx + 2048;      // weight staging (padded rows)
    float* sxi = sw + 10400;     // [16][256] xi -> xc
    float* szg = sxi + 4096;     // [16][256] z-gate -> y_act
    float* sdt = szg + 4096;     // [16][8]
    float* sB  = sdt + 128;      // [16][16]
    float* sC  = sB + 256;       // [16][16]

    const int tid = threadIdx.x;
    const int seq = blockIdx.x;
    const int b = seq / KKEEP;
    const int n = g_idx[b*KKEEP + (seq % KKEEP)];

    // gather input rows
    const float* xb = x + (size_t)b*TT*CC*HW + n;
    for (int i = tid; i < TT*CC; i += 256){
        sx[i] = xb[(size_t)i * HW];   // i = t*CC + c  -> offset (t*CC+c)*HW
    }
    __syncthreads();

    // rmsnorm (norm1)
    const int wid = tid >> 5, lane = tid & 31;
    for (int r = wid; r < TT; r += 8){
        float* row = sx + r*CC;
        float v0 = row[lane], v1 = row[lane+32], v2 = row[lane+64], v3 = row[lane+96];
        float ss = v0*v0 + v1*v1 + v2*v2 + v3*v3;
        ss += __shfl_xor_sync(0xffffffffu, ss, 16);
        ss += __shfl_xor_sync(0xffffffffu, ss, 8);
        ss += __shfl_xor_sync(0xffffffffu, ss, 4);
        ss += __shfl_xor_sync(0xffffffffu, ss, 2);
        ss += __shfl_xor_sync(0xffffffffu, ss, 1);
        float sc = rsqrtf(ss*(1.f/CC) + 1e-5f);
        row[lane]    = v0*sc*norm1_w[lane];
        row[lane+32] = v1*sc*norm1_w[lane+32];
        row[lane+64] = v2*sc*norm1_w[lane+64];
        row[lane+96] = v3*sc*norm1_w[lane+96];
    }
    __syncthreads();

    // in_proj: [16,128] @ [512,128]^T, 8 chunks of 64 output rows (smem staged, pad 132)
    {
        const int jl = tid & 63, tg = tid >> 6;
        for (int jc = 0; jc < 8; jc++){
            for (int i = tid; i < 64*128; i += 256){
                int r = i >> 7, c = i & 127;
                sw[r*132 + c] = in_w[(jc*64 + r)*128 + c];
            }
            __syncthreads();
            const float4* wr = (const float4*)(sw + jl*132);
            const int j = jc*64 + jl;
            for (int t = tg; t < TT; t += 4){
                const float4* xr = (const float4*)(sx + t*CC);
                float acc = 0.f;
                #pragma unroll
                for (int q = 0; q < 32; q++){
                    float4 a = xr[q], w = wr[q];
                    acc += a.x*w.x + a.y*w.y + a.z*w.z + a.w*w.w;
                }
                if (j < DI) sxi[t*DI + j] = acc;
                else        szg[t*DI + (j - DI)] = acc;
            }
            __syncthreads();
        }
    }

    // causal depthwise conv (k=4) + SiLU, per channel (thread d owns column d)
    {
        const int d = tid;
        const float w0 = conv_w[d*4], w1 = conv_w[d*4+1], w2 = conv_w[d*4+2], w3 = conv_w[d*4+3];
        const float cb = conv_b[d];
        float xv[TT+3];
        xv[0] = xv[1] = xv[2] = 0.f;
        #pragma unroll
        for (int t = 0; t < TT; t++) xv[t+3] = sxi[t*DI + d];
        #pragma unroll
        for (int t = 0; t < TT; t++){
            float a = cb + w0*xv[t] + w1*xv[t+1] + w2*xv[t+2] + w3*xv[t+3];
            sxi[t*DI + d] = a / (1.f + __expf(-a));   // silu
        }
    }
    __syncthreads();

    // x_proj: [16,256] @ [40,256]^T (stage all 40 rows, pad 260)
    {
        for (int i = tid; i < 40*DI; i += 256){
            int r = i >> 8, c = i & 255;
            sw[r*260 + c] = xp_w[i];
        }
        __syncthreads();
        for (int o = tid; o < TT*40; o += 256){
            int t = o / 40, j = o % 40;
            const float4* wr = (const float4*)(sw + j*260);
            const float4* xr = (const float4*)(sxi + t*DI);
            float acc = 0.f;
            #pragma unroll
            for (int q = 0; q < 64; q++){
                float4 a = xr[q], w = wr[q];
                acc += a.x*w.x + a.y*w.y + a.z*w.z + a.w*w.w;
            }
            if (j < 8)       sdt[t*8 + j] = acc;
            else if (j < 24) sB[t*16 + (j-8)] = acc;
            else             sC[t*16 + (j-24)] = acc;
        }
        __syncthreads();
    }

    // dt_proj + softplus + selective scan + gate (thread d owns channel d)
    {
        const int d = tid;
        float wdt[8];
        #pragma unroll
        for (int r = 0; r < 8; r++) wdt[r] = dt_w[d*8 + r];
        const float bdt = dt_b[d];
        float Ar[DS];
        #pragma unroll
        for (int s = 0; s < DS; s++) Ar[s] = -__expf(A_log[d*DS + s]);
        const float Dd = Dp[d];
        float h[DS];
        #pragma unroll
        for (int s = 0; s < DS; s++) h[s] = 0.f;
        for (int t = 0; t < TT; t++){
            float dtr = bdt;
            #pragma unroll
            for (int r = 0; r < 8; r++) dtr += sdt[t*8 + r]*wdt[r];
            float dtv = (dtr > 20.f) ? dtr : log1pf(__expf(dtr));  // softplus
            float xcv = sxi[t*DI + d];
            float coef = dtv * xcv;
            float y = 0.f;
            #pragma unroll
            for (int s = 0; s < DS; s++){
                float dA = __expf(dtv * Ar[s]);
                h[s] = dA*h[s] + coef*sB[t*16 + s];
                y += h[s]*sC[t*16 + s];
            }
            float zg = szg[t*DI + d];
            szg[t*DI + d] = (y + xcv*Dd) * (zg / (1.f + __expf(-zg)));
        }
    }
    __syncthreads();

    // out_proj: [16,256] @ [128,256]^T, 4 chunks of 32 output rows
    {
        const int cl = tid & 31, tg = tid >> 5;
        for (int oc = 0; oc < 4; oc++){
            for (int i = tid; i < 32*DI; i += 256){
                int r = i >> 8, c = i & 255;
                sw[r*260 + c] = out_w[(oc*32 + r)*DI + c];
            }
            __syncthreads();
            const float4* wr = (const float4*)(sw + cl*260);
            for (int t = tg; t < TT; t += 8){
                const float4* yr = (const float4*)(szg + t*DI);
                float acc = 0.f;
                #pragma unroll
                for (int q = 0; q < 64; q++){
                    float4 a = yr[q], w = wr[q];
                    acc += a.x*w.x + a.y*w.y + a.z*w.z + a.w*w.w;
                }
                g_zbuf[((size_t)seq*TT + t)*CC + oc*32 + cl] = acc;
            }
            __syncthreads();
        }
    }
}

// ---------------------------------------------------------------- mix MLP + scatter (2 sequences per block)
// smem floats: sz 4096 | sh1 4096 | swm 128*132=16896 = 25088 (100352 B)
#define SMEM_D_FLOATS 25088
__global__ void __launch_bounds__(256)
k_mix(const float* __restrict__ x,
      const float* __restrict__ norm2_w,
      const float* __restrict__ w1, const float* __restrict__ b1,
      const float* __restrict__ w2, const float* __restrict__ b2,
      float* __restrict__ out){
    extern __shared__ float sm[];
    float* sz  = sm;            // [2][16][128]
    float* sh1 = sz + 4096;     // [2][16][128]
    float* swm = sh1 + 4096;    // [128][132]

    const int tid = threadIdx.x;
    const int s0 = blockIdx.x * 2;
    int bb[2], nn[2];
    #pragma unroll
    for (int g = 0; g < 2; g++){
        int s = s0 + g;
        bb[g] = s / KKEEP;
        nn[g] = g_idx[bb[g]*KKEEP + (s % KKEEP)];
    }
    for (int g = 0; g < 2; g++)
        for (int i = tid; i < TT*CC; i += 256)
            sz[g*2048 + i] = g_zbuf[(size_t)(s0+g)*TT*CC + i];
    __syncthreads();

    // rmsnorm (norm2) over 32 rows
    const int wid = tid >> 5, lane = tid & 31;
    for (int r = wid; r < 32; r += 8){
        float* row = sz + r*CC;
        float v0 = row[lane], v1 = row[lane+32], v2 = row[lane+64], v3 = row[lane+96];
        float ss = v0*v0 + v1*v1 + v2*v2 + v3*v3;
        ss += __shfl_xor_sync(0xffffffffu, ss, 16);
        ss += __shfl_xor_sync(0xffffffffu, ss, 8);
        ss += __shfl_xor_sync(0xffffffffu, ss, 4);
        ss += __shfl_xor_sync(0xffffffffu, ss, 2);
        ss += __shfl_xor_sync(0xffffffffu, ss, 1);
        float sc = rsqrtf(ss*(1.f/CC) + 1e-5f);
        row[lane]    = v0*sc*norm2_w[lane];
        row[lane+32] = v1*sc*norm2_w[lane+32];
        row[lane+64] = v2*sc*norm2_w[lane+64];
        row[lane+96] = v3*sc*norm2_w[lane+96];
    }
    __syncthreads();

    // stage w1, GEMM + exact GELU
    for (int i = tid; i < CC*CC; i += 256)
        swm[(i >> 7)*132 + (i & 127)] = w1[i];
    __syncthreads();
    const int c = tid & 127, tg = tid >> 7;
    const float4* wr = (const float4*)(swm + c*132);
    for (int g = 0; g < 2; g++){
        for (int t = tg; t < TT; t += 2){
            const float4* zr = (const float4*)(sz + (g*TT + t)*CC);
            float acc = b1[c];
            #pragma unroll
            for (int q = 0; q < 32; q++){
                float4 a = zr[q], w = wr[q];
                acc += a.x*w.x + a.y*w.y + a.z*w.z + a.w*w.w;
            }
            sh1[(g*TT + t)*CC + c] = 0.5f*acc*(1.f + erff(acc*0.70710678118654752f));
        }
    }
    __syncthreads();

    // stage w2, GEMM + residual scatter
    for (int i = tid; i < CC*CC; i += 256)
        swm[(i >> 7)*132 + (i & 127)] = w2[i];
    __syncthreads();
    for (int g = 0; g < 2; g++){
        const size_t baseb = (size_t)bb[g]*TT*CC*HW + nn[g];
        for (int t = tg; t < TT; t += 2){
            const float4* hr = (const float4*)(sh1 + (g*TT + t)*CC);
            float acc = b2[c];
            #pragma unroll
            for (int q = 0; q < 32; q++){
                float4 a = hr[q], w = wr[q];
                acc += a.x*w.x + a.y*w.y + a.z*w.z + a.w*w.w;
            }
            size_t pos = baseb + (size_t)(t*CC + c)*HW;
            out[pos] = x[pos] + acc;
        }
    }
}

// ---------------------------------------------------------------- launch
extern "C" void kernel_launch(void* const* d_in, const int* in_sizes, int n_in,
                              void* d_out, int out_size){
    const float* x    = (const float*)d_in[0];
    const float* n1w  = (const float*)d_in[1];
    const float* n2w  = (const float*)d_in[2];
    const float* inw  = (const float*)d_in[3];
    const float* cw   = (const float*)d_in[4];
    const float* cb   = (const float*)d_in[5];
    const float* xpw  = (const float*)d_in[6];
    const float* dtw  = (const float*)d_in[7];
    const float* dtb  = (const float*)d_in[8];
    const float* alog = (const float*)d_in[9];
    const float* dp   = (const float*)d_in[10];
    const float* ow   = (const float*)d_in[11];
    const float* w1   = (const float*)d_in[12];
    const float* b1   = (const float*)d_in[13];
    const float* w2   = (const float*)d_in[14];
    const float* b2   = (const float*)d_in[15];
    float* out = (float*)d_out;

    cudaFuncSetAttribute(k_mamba, cudaFuncAttributeMaxDynamicSharedMemorySize, SMEM_C_FLOATS*4);
    cudaFuncSetAttribute(k_mix,   cudaFuncAttributeMaxDynamicSharedMemorySize, SMEM_D_FLOATS*4);

    const int n4 = out_size / 4;
    k_copy<<<(n4 + 255)/256, 256>>>((const float4*)x, (float4*)out, n4);
    k_energy<<<(BATCH*NPIX + 255)/256, 256>>>(x);
    k_select<<<BATCH, 768>>>();
    k_mamba<<<NSEQ, 256, SMEM_C_FLOATS*4>>>(x, n1w, inw, cw, cb, xpw, dtw, dtb, alog, dp, ow);
    k_mix<<<NSEQ/2, 256, SMEM_D_FLOATS*4>>>(x, n2w, w1, b1, w2, b2, out);
}

// round 3
// speedup vs baseline: 1.6159x; 1.6159x over previous
#include <cuda_runtime.h>
#include <math.h>

#define BATCH 2
#define TT 16
#define CC 128
#define HW 2304
#define NPIX 2304
#define DI 256
#define DS 16
#define KKEEP 1152
#define NSEQ (BATCH*KKEEP)

// scratch (static device globals; no allocations allowed)
__device__ float g_energy[BATCH*NPIX];
__device__ int   g_idx[BATCH*KKEEP];
__device__ float g_zbuf[(size_t)NSEQ*TT*CC];

// ---------------------------------------------------------------- copy base
__global__ void k_copy(const float4* __restrict__ src, float4* __restrict__ dst, int n4){
    int i = blockIdx.x*blockDim.x + threadIdx.x;
    if (i < n4) dst[i] = src[i];
}

// ---------------------------------------------------------------- energy
__global__ void k_energy(const float* __restrict__ x){
    int id = blockIdx.x*blockDim.x + threadIdx.x;
    if (id >= BATCH*NPIX) return;
    int b = id / NPIX, n = id % NPIX;
    const float* xb = x + (size_t)b*TT*CC*HW + n;
    float e = 0.f;
    for (int t = 0; t < TT; t++){
        const float* xt = xb + (size_t)t*CC*HW;
        float ss = 0.f;
        #pragma unroll 8
        for (int c = 0; c < CC; c++){
            float v = xt[(size_t)c*HW];
            ss += v*v;
        }
        e += sqrtf(ss);
    }
    g_energy[id] = e * (1.f/TT);
}

// ---------------------------------------------------------------- select top-K (stable rank), sorted index output
__global__ void k_select(){
    __shared__ float se[NPIX];
    __shared__ int scnt[768];
    int b = blockIdx.x, tid = threadIdx.x;   // 768 threads, 3 pixels each
    for (int i = tid; i < NPIX; i += 768) se[i] = g_energy[b*NPIX + i];
    __syncthreads();
    int n0 = tid*3;
    float e0 = se[n0], e1 = se[n0+1], e2 = se[n0+2];
    int r0 = 0, r1 = 0, r2 = 0;
    for (int m = 0; m < NPIX; m++){
        float em = se[m];
        r0 += (em > e0) || (em == e0 && m < n0);
        r1 += (em > e1) || (em == e1 && m < n0+1);
        r2 += (em > e2) || (em == e2 && m < n0+2);
    }
    int k0 = r0 < KKEEP, k1 = r1 < KKEEP, k2 = r2 < KKEEP;
    int cnt = k0 + k1 + k2;
    scnt[tid] = cnt;
    __syncthreads();
    for (int off = 1; off < 768; off <<= 1){
        int add = (tid >= off) ? scnt[tid-off] : 0;
        __syncthreads();
        scnt[tid] += add;
        __syncthreads();
    }
    int pos = scnt[tid] - cnt;
    if (k0) g_idx[b*KKEEP + pos++] = n0;
    if (k1) g_idx[b*KKEEP + pos++] = n0+1;
    if (k2) g_idx[b*KKEEP + pos++] = n0+2;
}

// ---------------------------------------------------------------- fused mamba per sequence
// smem floats: sx 2048 | sw 16640 | sxi 4096 | szg 4096 | sdt 128 | sB 256 | sC 256 = 27520 (110080 B)
#define SMEM_C_FLOATS 27520
__global__ void __launch_bounds__(256, 2)
k_mamba(const float* __restrict__ x,
        const float* __restrict__ norm1_w,
        const float* __restrict__ in_w,
        const float* __restrict__ conv_w,
        const float* __restrict__ conv_b,
        const float* __restrict__ xp_w,
        const float* __restrict__ dt_w,
        const float* __restrict__ dt_b,
        const float* __restrict__ A_log,
        const float* __restrict__ Dp,
        const float* __restrict__ out_w){
    extern __shared__ float sm[];
    float* sx  = sm;             // [16][128]
    float* sw  = sx + 2048;      // weight staging (padded rows), up to 64x260
    float* sxi = sw + 16640;     // [16][256] xi -> xc
    float* szg = sxi + 4096;     // [16][256] z-gate -> y_act
    float* sdt = szg + 4096;     // [16][8]
    float* sB  = sdt + 128;      // [16][16]
    float* sC  = sB + 256;       // [16][16]

    const int tid = threadIdx.x;
    const int seq = blockIdx.x;
    const int b = seq / KKEEP;
    const int n = g_idx[b*KKEEP + (seq % KKEEP)];
    const int jl = tid & 63, tg = tid >> 6;   // 64 cols x 4 t-groups

    // gather input rows
    const float* xb = x + (size_t)b*TT*CC*HW + n;
    for (int i = tid; i < TT*CC; i += 256){
        sx[i] = xb[(size_t)i * HW];
    }
    __syncthreads();

    // rmsnorm (norm1)
    const int wid = tid >> 5, lane = tid & 31;
    for (int r = wid; r < TT; r += 8){
        float* row = sx + r*CC;
        float v0 = row[lane], v1 = row[lane+32], v2 = row[lane+64], v3 = row[lane+96];
        float ss = v0*v0 + v1*v1 + v2*v2 + v3*v3;
        ss += __shfl_xor_sync(0xffffffffu, ss, 16);
        ss += __shfl_xor_sync(0xffffffffu, ss, 8);
        ss += __shfl_xor_sync(0xffffffffu, ss, 4);
        ss += __shfl_xor_sync(0xffffffffu, ss, 2);
        ss += __shfl_xor_sync(0xffffffffu, ss, 1);
        float sc = rsqrtf(ss*(1.f/CC) + 1e-5f);
        row[lane]    = v0*sc*norm1_w[lane];
        row[lane+32] = v1*sc*norm1_w[lane+32];
        row[lane+64] = v2*sc*norm1_w[lane+64];
        row[lane+96] = v3*sc*norm1_w[lane+96];
    }
    __syncthreads();

    // in_proj: [16,128] @ [512,128]^T, 8 chunks of 64 rows, register-tiled over 4 t
    {
        const float4* x0 = (const float4*)(sx + (tg*4+0)*CC);
        const float4* x1 = (const float4*)(sx + (tg*4+1)*CC);
        const float4* x2 = (const float4*)(sx + (tg*4+2)*CC);
        const float4* x3 = (const float4*)(sx + (tg*4+3)*CC);
        for (int jc = 0; jc < 8; jc++){
            for (int i = tid; i < 64*128; i += 256){
                int r = i >> 7, c = i & 127;
                sw[r*132 + c] = in_w[(jc*64 + r)*128 + c];
            }
            __syncthreads();
            const float4* wr = (const float4*)(sw + jl*132);
            float a0 = 0.f, a1 = 0.f, a2 = 0.f, a3 = 0.f;
            #pragma unroll 8
            for (int q = 0; q < 32; q++){
                float4 w = wr[q];
                float4 v = x0[q];
                a0 += v.x*w.x + v.y*w.y + v.z*w.z + v.w*w.w;
                v = x1[q];
                a1 += v.x*w.x + v.y*w.y + v.z*w.z + v.w*w.w;
                v = x2[q];
                a2 += v.x*w.x + v.y*w.y + v.z*w.z + v.w*w.w;
                v = x3[q];
                a3 += v.x*w.x + v.y*w.y + v.z*w.z + v.w*w.w;
            }
            int j = jc*64 + jl;
            float* dst = (j < DI) ? (sxi + j) : (szg + (j - DI));
            dst[(tg*4+0)*DI] = a0;
            dst[(tg*4+1)*DI] = a1;
            dst[(tg*4+2)*DI] = a2;
            dst[(tg*4+3)*DI] = a3;
            __syncthreads();
        }
    }

    // causal depthwise conv (k=4) + SiLU, per channel
    {
        const int d = tid;
        const float w0 = conv_w[d*4], w1 = conv_w[d*4+1], w2 = conv_w[d*4+2], w3 = conv_w[d*4+3];
        const float cb = conv_b[d];
        float xv[TT+3];
        xv[0] = xv[1] = xv[2] = 0.f;
        #pragma unroll
        for (int t = 0; t < TT; t++) xv[t+3] = sxi[t*DI + d];
        #pragma unroll
        for (int t = 0; t < TT; t++){
            float a = cb + w0*xv[t] + w1*xv[t+1] + w2*xv[t+2] + w3*xv[t+3];
            sxi[t*DI + d] = a / (1.f + __expf(-a));
        }
    }
    __syncthreads();

    // x_proj: [16,256] @ [40,256]^T, register-tiled over 4 t (threads jl>=40 idle)
    {
        for (int i = tid; i < 40*DI; i += 256){
            int r = i >> 8, c = i & 255;
            sw[r*260 + c] = xp_w[i];
        }
        __syncthreads();
        if (jl < 40){
            const float4* wr = (const float4*)(sw + jl*260);
            const float4* y0 = (const float4*)(sxi + (tg*4+0)*DI);
            const float4* y1 = (const float4*)(sxi + (tg*4+1)*DI);
            const float4* y2 = (const float4*)(sxi + (tg*4+2)*DI);
            const float4* y3 = (const float4*)(sxi + (tg*4+3)*DI);
            float a0 = 0.f, a1 = 0.f, a2 = 0.f, a3 = 0.f;
            #pragma unroll 8
            for (int q = 0; q < 64; q++){
                float4 w = wr[q];
                float4 v = y0[q];
                a0 += v.x*w.x + v.y*w.y + v.z*w.z + v.w*w.w;
                v = y1[q];
                a1 += v.x*w.x + v.y*w.y + v.z*w.z + v.w*w.w;
                v = y2[q];
                a2 += v.x*w.x + v.y*w.y + v.z*w.z + v.w*w.w;
                v = y3[q];
                a3 += v.x*w.x + v.y*w.y + v.z*w.z + v.w*w.w;
            }
            #pragma unroll
            for (int u = 0; u < 4; u++){
                int t = tg*4 + u;
                float acc = (u == 0) ? a0 : (u == 1) ? a1 : (u == 2) ? a2 : a3;
                if (jl < 8)       sdt[t*8 + jl] = acc;
                else if (jl < 24) sB[t*16 + (jl-8)] = acc;
                else              sC[t*16 + (jl-24)] = acc;
            }
        }
        __syncthreads();
    }

    // dt_proj + softplus + selective scan + gate (thread d owns channel d)
    {
        const int d = tid;
        float wdt[8];
        #pragma unroll
        for (int r = 0; r < 8; r++) wdt[r] = dt_w[d*8 + r];
        const float bdt = dt_b[d];
        float Ar[DS];
        #pragma unroll
        for (int s = 0; s < DS; s++) Ar[s] = -__expf(A_log[d*DS + s]);
        const float Dd = Dp[d];
        float h[DS];
        #pragma unroll
        for (int s = 0; s < DS; s++) h[s] = 0.f;
        for (int t = 0; t < TT; t++){
            float dtr = bdt;
            #pragma unroll
            for (int r = 0; r < 8; r++) dtr += sdt[t*8 + r]*wdt[r];
            float dtv = (dtr > 20.f) ? dtr : log1pf(__expf(dtr));
            float xcv = sxi[t*DI + d];
            float coef = dtv * xcv;
            float y = 0.f;
            #pragma unroll
            for (int s = 0; s < DS; s++){
                float dA = __expf(dtv * Ar[s]);
                h[s] = dA*h[s] + coef*sB[t*16 + s];
                y += h[s]*sC[t*16 + s];
            }
            float zg = szg[t*DI + d];
            szg[t*DI + d] = (y + xcv*Dd) * (zg / (1.f + __expf(-zg)));
        }
    }
    __syncthreads();

    // out_proj: [16,256] @ [128,256]^T, 2 chunks of 64 rows, register-tiled over 4 t
    {
        const float4* y0 = (const float4*)(szg + (tg*4+0)*DI);
        const float4* y1 = (const float4*)(szg + (tg*4+1)*DI);
        const float4* y2 = (const float4*)(szg + (tg*4+2)*DI);
        const float4* y3 = (const float4*)(szg + (tg*4+3)*DI);
        for (int oc = 0; oc < 2; oc++){
            for (int i = tid; i < 64*DI; i += 256){
                int r = i >> 8, c = i & 255;
                sw[r*260 + c] = out_w[(oc*64 + r)*DI + c];
            }
            __syncthreads();
            const float4* wr = (const float4*)(sw + jl*260);
            float a0 = 0.f, a1 = 0.f, a2 = 0.f, a3 = 0.f;
            #pragma unroll 8
            for (int q = 0; q < 64; q++){
                float4 w = wr[q];
                float4 v = y0[q];
                a0 += v.x*w.x + v.y*w.y + v.z*w.z + v.w*w.w;
                v = y1[q];
                a1 += v.x*w.x + v.y*w.y + v.z*w.z + v.w*w.w;
                v = y2[q];
                a2 += v.x*w.x + v.y*w.y + v.z*w.z + v.w*w.w;
                v = y3[q];
                a3 += v.x*w.x + v.y*w.y + v.z*w.z + v.w*w.w;
            }
            float* zb = g_zbuf + (size_t)seq*TT*CC + oc*64 + jl;
            zb[(tg*4+0)*CC] = a0;
            zb[(tg*4+1)*CC] = a1;
            zb[(tg*4+2)*CC] = a2;
            zb[(tg*4+3)*CC] = a3;
            __syncthreads();
        }
    }
}

// ---------------------------------------------------------------- mix MLP + scatter (2 sequences per block)
// smem floats: sz 4096 | sh1 4096 | swm 128*132=16896 = 25088 (100352 B)
#define SMEM_D_FLOATS 25088
__global__ void __launch_bounds__(256, 2)
k_mix(const float* __restrict__ x,
      const float* __restrict__ norm2_w,
      const float* __restrict__ w1, const float* __restrict__ b1,
      const float* __restrict__ w2, const float* __restrict__ b2,
      float* __restrict__ out){
    extern __shared__ float sm[];
    float* sz  = sm;            // [2][16][128]
    float* sh1 = sz + 4096;     // [2][16][128]
    float* swm = sh1 + 4096;    // [128][132]

    const int tid = threadIdx.x;
    const int s0 = blockIdx.x * 2;
    int bb[2], nn[2];
    #pragma unroll
    for (int g = 0; g < 2; g++){
        int s = s0 + g;
        bb[g] = s / KKEEP;
        nn[g] = g_idx[bb[g]*KKEEP + (s % KKEEP)];
    }
    for (int g = 0; g < 2; g++)
        for (int i = tid; i < TT*CC; i += 256)
            sz[g*2048 + i] = g_zbuf[(size_t)(s0+g)*TT*CC + i];
    __syncthreads();

    // rmsnorm (norm2) over 32 rows
    const int wid = tid >> 5, lane = tid & 31;
    for (int r = wid; r < 32; r += 8){
        float* row = sz + r*CC;
        float v0 = row[lane], v1 = row[lane+32], v2 = row[lane+64], v3 = row[lane+96];
        float ss = v0*v0 + v1*v1 + v2*v2 + v3*v3;
        ss += __shfl_xor_sync(0xffffffffu, ss, 16);
        ss += __shfl_xor_sync(0xffffffffu, ss, 8);
        ss += __shfl_xor_sync(0xffffffffu, ss, 4);
        ss += __shfl_xor_sync(0xffffffffu, ss, 2);
        ss += __shfl_xor_sync(0xffffffffu, ss, 1);
        float sc = rsqrtf(ss*(1.f/CC) + 1e-5f);
        row[lane]    = v0*sc*norm2_w[lane];
        row[lane+32] = v1*sc*norm2_w[lane+32];
        row[lane+64] = v2*sc*norm2_w[lane+64];
        row[lane+96] = v3*sc*norm2_w[lane+96];
    }
    __syncthreads();

    const int c = tid & 127, tg = tid >> 7;   // 128 cols x 2 t-groups (8 t each)

    // stage w1, GEMM + exact GELU (register-tiled over 8 t)
    for (int i = tid; i < CC*CC; i += 256)
        swm[(i >> 7)*132 + (i & 127)] = w1[i];
    __syncthreads();
    {
        const float4* wr = (const float4*)(swm + c*132);
        for (int g = 0; g < 2; g++){
            const float* zp = sz + g*2048 + tg*8*CC;
            float acc[8];
            #pragma unroll
            for (int i = 0; i < 8; i++) acc[i] = b1[c];
            #pragma unroll 8
            for (int q = 0; q < 32; q++){
                float4 w = wr[q];
                #pragma unroll
                for (int i = 0; i < 8; i++){
                    float4 a = ((const float4*)(zp + i*CC))[q];
                    acc[i] += a.x*w.x + a.y*w.y + a.z*w.z + a.w*w.w;
                }
            }
            #pragma unroll
            for (int i = 0; i < 8; i++){
                float v = acc[i];
                sh1[(g*TT + tg*8 + i)*CC + c] = 0.5f*v*(1.f + erff(v*0.70710678118654752f));
            }
        }
    }
    __syncthreads();

    // stage w2, GEMM + residual scatter (register-tiled over 8 t)
    for (int i = tid; i < CC*CC; i += 256)
        swm[(i >> 7)*132 + (i & 127)] = w2[i];
    __syncthreads();
    {
        const float4* wr = (const float4*)(swm + c*132);
        for (int g = 0; g < 2; g++){
            const float* hp = sh1 + g*2048 + tg*8*CC;
            float acc[8];
            #pragma unroll
            for (int i = 0; i < 8; i++) acc[i] = b2[c];
            #pragma unroll 8
            for (int q = 0; q < 32; q++){
                float4 w = wr[q];
                #pragma unroll
                for (int i = 0; i < 8; i++){
                    float4 a = ((const float4*)(hp + i*CC))[q];
                    acc[i] += a.x*w.x + a.y*w.y + a.z*w.z + a.w*w.w;
                }
            }
            const size_t baseb = (size_t)bb[g]*TT*CC*HW + nn[g];
            #pragma unroll
            for (int i = 0; i < 8; i++){
                int t = tg*8 + i;
                size_t pos = baseb + (size_t)(t*CC + c)*HW;
                out[pos] = x[pos] + acc[i];
            }
        }
    }
}

// ---------------------------------------------------------------- launch
extern "C" void kernel_launch(void* const* d_in, const int* in_sizes, int n_in,
                              void* d_out, int out_size){
    const float* x    = (const float*)d_in[0];
    const float* n1w  = (const float*)d_in[1];
    const float* n2w  = (const float*)d_in[2];
    const float* inw  = (const float*)d_in[3];
    const float* cw   = (const float*)d_in[4];
    const float* cb   = (const float*)d_in[5];
    const float* xpw  = (const float*)d_in[6];
    const float* dtw  = (const float*)d_in[7];
    const float* dtb  = (const float*)d_in[8];
    const float* alog = (const float*)d_in[9];
    const float* dp   = (const float*)d_in[10];
    const float* ow   = (const float*)d_in[11];
    const float* w1   = (const float*)d_in[12];
    const float* b1   = (const float*)d_in[13];
    const float* w2   = (const float*)d_in[14];
    const float* b2   = (const float*)d_in[15];
    float* out = (float*)d_out;

    cudaFuncSetAttribute(k_mamba, cudaFuncAttributeMaxDynamicSharedMemorySize, SMEM_C_FLOATS*4);
    cudaFuncSetAttribute(k_mix,   cudaFuncAttributeMaxDynamicSharedMemorySize, SMEM_D_FLOATS*4);

    const int n4 = out_size / 4;
    k_copy<<<(n4 + 255)/256, 256>>>((const float4*)x, (float4*)out, n4);
    k_energy<<<(BATCH*NPIX + 255)/256, 256>>>(x);
    k_select<<<BATCH, 768>>>();
    k_mamba<<<NSEQ, 256, SMEM_C_FLOATS*4>>>(x, n1w, inw, cw, cb, xpw, dtw, dtb, alog, dp, ow);
    k_mix<<<NSEQ/2, 256, SMEM_D_FLOATS*4>>>(x, n2w, w1, b1, w2, b2, out);
}